// round 8
// baseline (speedup 1.0000x reference)
#include <cuda_runtime.h>
#include <stdint.h>
#include <math.h>

#define DN 256
#define NN 128
#define SD 132            // scratch row stride (floats)
#define NTHREADS 512
#define NWARPS 16
#define SMEM_BYTES (129 * SD * 4)

// Master matrix: G eliminated through current front t (device-global scratch).
__device__ float g_A[DN * DN];
// Shadow diagonal chain: (G[q,q]-1) + identical update chain (ref has -1 from step 0).
__device__ float g_dv1[DN];
// Precomputed gumbel noise per (step k, position i) — data independent.
__device__ float g_gum[NN * DN];

// ---------------------------------------------------------------------------
// Threefry-2x32, 20 rounds (JAX-compatible)
// ---------------------------------------------------------------------------
__device__ __forceinline__ void threefry(uint32_t k0, uint32_t k1,
                                         uint32_t x0, uint32_t x1,
                                         uint32_t &o0, uint32_t &o1)
{
    uint32_t ks2 = k0 ^ k1 ^ 0x1BD11BDAu;
#define TFR(r) { x0 += x1; x1 = (x1 << r) | (x1 >> (32 - r)); x1 ^= x0; }
    x0 += k0; x1 += k1;
    TFR(13) TFR(15) TFR(26) TFR(6)
    x0 += k1;  x1 += ks2 + 1u;
    TFR(17) TFR(29) TFR(16) TFR(24)
    x0 += ks2; x1 += k0 + 2u;
    TFR(13) TFR(15) TFR(26) TFR(6)
    x0 += k0;  x1 += k1 + 3u;
    TFR(17) TFR(29) TFR(16) TFR(24)
    x0 += k1;  x1 += ks2 + 4u;
    TFR(13) TFR(15) TFR(26) TFR(6)
    x0 += ks2; x1 += k0 + 5u;
#undef TFR
    o0 = x0; o1 = x1;
}

// ---------------------------------------------------------------------------
// G = I - P P^T  (exact fp32, serial ascending-k fma accumulation)
// ---------------------------------------------------------------------------
__global__ void g_init_kernel(const float* __restrict__ P)
{
    __shared__ float Ta[16][129];
    __shared__ float Tb[16][129];
    const int bi = blockIdx.y * 16;
    const int bj = blockIdx.x * 16;
    for (int e = threadIdx.x; e < 16 * 128; e += 256) {
        int r = e >> 7, c = e & 127;
        Ta[r][c] = P[(bi + r) * 128 + c];
        Tb[r][c] = P[(bj + r) * 128 + c];
    }
    __syncthreads();
    const int ty = threadIdx.x >> 4, tx = threadIdx.x & 15;
    float acc = 0.0f;
#pragma unroll 8
    for (int m = 0; m < 128; m++)
        acc = __fmaf_rn(Ta[ty][m], Tb[tx][m], acc);
    const int gi = bi + ty, gj = bj + tx;
    g_A[gi * DN + gj] = __fsub_rn((gi == gj) ? 1.0f : 0.0f, acc);
}

// ---------------------------------------------------------------------------
// Precompute gumbel noise — JAX partitionable threefry bits path (bit-exact)
// ---------------------------------------------------------------------------
__global__ void gumbel_init_kernel()
{
    const int k = blockIdx.x;      // step
    const int i = threadIdx.x;     // position 0..255
    uint32_t kk0, kk1;
    threefry(0u, 42u, 0u, (uint32_t)k, kk0, kk1);     // fold_in(key(42), k)
    uint32_t o0, o1;
    threefry(kk0, kk1, 0u, (uint32_t)i, o0, o1);      // counter64 = i
    const uint32_t bits = o0 ^ o1;                     // 64->32 fold
    const float f = __uint_as_float((bits >> 9) | 0x3f800000u) - 1.0f;
    const float TINYF = 1.17549435e-38f;
    const float uu = fmaxf(TINYF, __fadd_rn(f, TINYF));
    const float nl = (float)(-log((double)uu));
    const float g  = -(float)(log((double)nl));
    g_gum[k * DN + i] = g;
}

__device__ __forceinline__ float piv_safe_rcp(float pv)
{
    const float pvs = (fabsf(pv) > 1e-30f) ? pv : 1e-30f;
    return __frcp_rn(pvs);
}

// ---------------------------------------------------------------------------
// Persistent single-CTA sampler: 128 sequential steps (incremental front).
// Spec LU = blocked panels (b=8): register strip factor by warp 0, TRSM by
// threads, trailing register-chain GEMM by all warps. No spin-waiting.
// ---------------------------------------------------------------------------
__global__ __launch_bounds__(NTHREADS, 1)
void sampler_kernel(float* __restrict__ out, int out_size)
{
    extern __shared__ float S[];          // scratch block, SD-stride rows
    __shared__ float piv[DN];
    __shared__ float occ[DN];
    __shared__ float sh_rinv;
    __shared__ int   sh_t, sh_pos;
    __shared__ float sh_ps;

    const int tid = threadIdx.x;
    const int wid = tid >> 5, lid = tid & 31;
    const float NEGINF = __int_as_float(0xff800000);

    for (int i = tid; i < DN; i += NTHREADS) {
        occ[i] = 0.0f;
        g_dv1[i] = __fsub_rn(g_A[i * DN + i], 1.0f);
    }
    if (tid == 0) { sh_t = 0; sh_ps = 1.0f; }
    __syncthreads();

    for (int k = 0; k < NN; k++) {
        const int t = sh_t;
        const int xmax = DN - NN + k + 1;   // 129 + k
        const int s = xmax - t;             // <= 129

        // ---- copy active master block [t:xmax)^2 into shared scratch ----
        for (int r = wid; r < s; r += NWARPS) {
            const float* src = g_A + (t + r) * DN + t;
            float* dst = S + r * SD;
            for (int c = lid; c < s; c += 32) dst[c] = src[c];
        }
        __syncthreads();

        // ---- blocked speculative elimination ----
        for (int j0 = 0; j0 < s; j0 += 8) {
            const int bw = (s - j0 < 8) ? (s - j0) : 8;
            const int jend = j0 + bw;
            const int nr = s - j0;          // strip rows

            // === phase 1: strip factor (warp 0, registers) ===
            if (wid == 0) {
                float rg[5][8];
#pragma unroll
                for (int m = 0; m < 5; m++) {
                    const int rr = lid + 32 * m;
                    if (rr < nr) {
                        const float* src = S + (j0 + rr) * SD + j0;
#pragma unroll
                        for (int c = 0; c < 8; c++)
                            rg[m][c] = (c < bw) ? src[c] : 0.0f;
                    } else {
#pragma unroll
                        for (int c = 0; c < 8; c++) rg[m][c] = 0.0f;
                    }
                }
#pragma unroll
                for (int jj = 0; jj < 8; jj++) {
                    if (jj >= bw) break;
                    const float pv = __shfl_sync(0xffffffffu, rg[0][jj], jj);
                    if (lid == jj) piv[t + j0 + jj] = pv;
                    const float rinv = piv_safe_rcp(pv);
                    float li[5];
#pragma unroll
                    for (int m = 0; m < 5; m++) {
                        const int rr = lid + 32 * m;
                        li[m] = 0.0f;
                        if (rr < nr && rr > jj) {
                            li[m] = __fmul_rn(rg[m][jj], rinv);
                            rg[m][jj] = li[m];
                        }
                    }
#pragma unroll
                    for (int c = jj + 1; c < 8; c++) {
                        const float ucv = __shfl_sync(0xffffffffu, rg[0][c], jj);
                        if (c < bw) {
#pragma unroll
                            for (int m = 0; m < 5; m++) {
                                const int rr = lid + 32 * m;
                                if (rr < nr && rr > jj)
                                    rg[m][c] = __fmaf_rn(-li[m], ucv, rg[m][c]);
                            }
                        }
                    }
                }
                // store strip back
#pragma unroll
                for (int m = 0; m < 5; m++) {
                    const int rr = lid + 32 * m;
                    if (rr < nr) {
                        float* dst = S + (j0 + rr) * SD + j0;
#pragma unroll
                        for (int c = 0; c < 8; c++)
                            if (c < bw) dst[c] = rg[m][c];
                    }
                }
            }
            __syncthreads();

            if (jend >= s) break;           // nothing beyond panel

            // === phase 2: TRSM — pivot rows j0..jend-1, cols jend..s ===
            {
                const int c = jend + tid;
                if (c < s) {
                    float uv[8];
                    uv[0] = S[j0 * SD + c];
#pragma unroll
                    for (int m = 1; m < 8; m++) {
                        if (m < bw) {
                            float v = S[(j0 + m) * SD + c];
#pragma unroll
                            for (int mm = 0; mm < 7; mm++) {
                                if (mm < m) {
                                    const float l = S[(j0 + m) * SD + j0 + mm];
                                    v = __fmaf_rn(-l, uv[mm], v);
                                }
                            }
                            S[(j0 + m) * SD + c] = v;
                            uv[m] = v;
                        }
                    }
                }
            }
            __syncthreads();

            // === phase 3: trailing update rows/cols jend..s ===
            if (bw == 8) {
                for (int i = jend + wid; i < s; i += NWARPS) {
                    const float* lr = S + i * SD + j0;
                    float lv[8];
#pragma unroll
                    for (int m = 0; m < 8; m++) lv[m] = lr[m];
                    float* row = S + i * SD;
                    for (int cc = jend + lid; cc < s; cc += 32) {
                        float acc = row[cc];
#pragma unroll
                        for (int m = 0; m < 8; m++)
                            acc = __fmaf_rn(-lv[m], S[(j0 + m) * SD + cc], acc);
                        row[cc] = acc;
                    }
                }
            } else {
                for (int i = jend + wid; i < s; i += NWARPS) {
                    const float* lr = S + i * SD + j0;
                    float lv[8];
#pragma unroll
                    for (int m = 0; m < 8; m++) lv[m] = (m < bw) ? lr[m] : 0.0f;
                    float* row = S + i * SD;
                    for (int cc = jend + lid; cc < s; cc += 32) {
                        float acc = row[cc];
#pragma unroll
                        for (int m = 0; m < 8; m++)
                            if (m < bw)
                                acc = __fmaf_rn(-lv[m], S[(j0 + m) * SD + cc], acc);
                        row[cc] = acc;
                    }
                }
            }
            __syncthreads();
        }
        __syncthreads();

        // ---- single-warp sampling: scan + probs + gumbel argmax ----
        if (wid == 0) {
            const int ch = (s + 31) >> 5;         // <= 5 slots per lane
            const int lo = lid * ch;
            float u[5], gum[5];
            float lp = 1.0f;
#pragma unroll
            for (int m = 0; m < 5; m++) {
                const int idx = lo + m;
                const bool ok = (m < ch) && (idx < s);
                u[m]   = ok ? piv[t + idx] : 1.0f;
                gum[m] = ok ? g_gum[k * DN + (t + idx)] : 0.0f;
                lp = __fmul_rn(lp, u[m]);
            }
            float run = lp;
            for (int d = 1; d < 32; d <<= 1) {
                const float v = __shfl_up_sync(0xffffffffu, run, d);
                if (lid >= d) run = __fmul_rn(v, run);
            }
            float c = __shfl_up_sync(0xffffffffu, run, 1);
            if (lid == 0) c = 1.0f;

            float best = NEGINF, bprob = 0.0f;
            int bidx = 1 << 30;
#pragma unroll
            for (int m = 0; m < 5; m++) {
                const int idx = lo + m;
                if (m < ch && idx < s) {
                    float p = __fmul_rn(__fsub_rn(1.0f, u[m]), c);
                    p = (fabsf(p) > 1e-15f) ? p : 0.0f;
                    c = __fmul_rn(c, u[m]);
                    if (p > 0.0f) {
                        const float vv = __fadd_rn(gum[m], logf(p));
                        if (vv > best) { best = vv; bidx = idx; bprob = p; }
                    }
                }
            }
            for (int off = 16; off; off >>= 1) {
                const float ov = __shfl_down_sync(0xffffffffu, best, off);
                const int   oi = __shfl_down_sync(0xffffffffu, bidx, off);
                const float op = __shfl_down_sync(0xffffffffu, bprob, off);
                if (ov > best || (ov == best && oi < bidx)) { best = ov; bidx = oi; bprob = op; }
            }
            if (lid == 0) {
                const int pos = (bidx == (1 << 30)) ? 0 : (t + bidx);
                const float psel = (bidx == (1 << 30)) ? 0.0f : bprob;
                sh_pos = pos;
                occ[pos] = 1.0f;
                sh_ps = __fmul_rn(sh_ps, psel);
            }
        }
        __syncthreads();

        // ---- commit rows t..pos into master (advance front to pos+1) ----
        const int pos = sh_pos;
        if (k < NN - 1) {
            for (int j = t; j <= pos; j++) {
                if (tid == 0) {
                    if (j == pos)
                        g_A[pos * DN + pos] = g_dv1[pos];   // -1-from-step-0 chain
                    sh_rinv = piv_safe_rcp(g_A[j * DN + j]);
                }
                __syncthreads();
                const float rinv = sh_rinv;
                const int cc = j + 1 + lid;
                const float* uro = g_A + j * DN;
                float uu[8];
#pragma unroll
                for (int m = 0; m < 8; m++) {
                    const int c = cc + 32 * m;
                    uu[m] = (c < DN) ? uro[c] : 0.0f;
                }
                for (int i = j + 1 + wid; i < DN; i += NWARPS) {
                    const float li = __fmul_rn(g_A[i * DN + j], rinv);
                    float* row = g_A + i * DN;
#pragma unroll
                    for (int m = 0; m < 8; m++) {
                        const int c = cc + 32 * m;
                        if (c < DN) {
                            row[c] = __fmaf_rn(-li, uu[m], row[c]);
                            if (c == i) g_dv1[i] = __fmaf_rn(-li, uu[m], g_dv1[i]);
                        }
                    }
                }
                __syncthreads();
            }
            if (tid == 0) sh_t = pos + 1;
        }
        __syncthreads();
    }

    // ---- outputs: occ_vec (256) then prob_sample (1) ----
    for (int i = tid; i < DN && i < out_size; i += NTHREADS) out[i] = occ[i];
    if (tid == 0 && out_size > DN) out[DN] = sh_ps;
    for (int i = DN + 1 + tid; i < out_size; i += NTHREADS) out[i] = 0.0f;
}

// ---------------------------------------------------------------------------
extern "C" void kernel_launch(void* const* d_in, const int* in_sizes, int n_in,
                              void* d_out, int out_size)
{
    const float* P = (const float*)d_in[0];
    float* out = (float*)d_out;

    cudaFuncSetAttribute(sampler_kernel,
                         cudaFuncAttributeMaxDynamicSharedMemorySize,
                         SMEM_BYTES);

    g_init_kernel<<<dim3(16, 16), 256>>>(P);
    gumbel_init_kernel<<<NN, DN>>>();
    sampler_kernel<<<1, NTHREADS, SMEM_BYTES>>>(out, out_size);
}

// round 9
// speedup vs baseline: 1.0499x; 1.0499x over previous
#include <cuda_runtime.h>
#include <stdint.h>
#include <math.h>

#define DN 256
#define NN 128
#define SD 132            // scratch row stride (floats)
#define NTHREADS 1024
#define NWARPS 32
#define SMEM_BYTES (129 * SD * 4)

// Master matrix: G eliminated through current front t (device-global scratch).
__device__ float g_A[DN * DN];
// Shadow diagonal chain: (G[q,q]-1) + identical update chain (ref has -1 from step 0).
__device__ float g_dv1[DN];
// Precomputed gumbel noise per (step k, position i) — data independent.
__device__ float g_gum[NN * DN];

// ---------------------------------------------------------------------------
// Threefry-2x32, 20 rounds (JAX-compatible)
// ---------------------------------------------------------------------------
__device__ __forceinline__ void threefry(uint32_t k0, uint32_t k1,
                                         uint32_t x0, uint32_t x1,
                                         uint32_t &o0, uint32_t &o1)
{
    uint32_t ks2 = k0 ^ k1 ^ 0x1BD11BDAu;
#define TFR(r) { x0 += x1; x1 = (x1 << r) | (x1 >> (32 - r)); x1 ^= x0; }
    x0 += k0; x1 += k1;
    TFR(13) TFR(15) TFR(26) TFR(6)
    x0 += k1;  x1 += ks2 + 1u;
    TFR(17) TFR(29) TFR(16) TFR(24)
    x0 += ks2; x1 += k0 + 2u;
    TFR(13) TFR(15) TFR(26) TFR(6)
    x0 += k0;  x1 += k1 + 3u;
    TFR(17) TFR(29) TFR(16) TFR(24)
    x0 += k1;  x1 += ks2 + 4u;
    TFR(13) TFR(15) TFR(26) TFR(6)
    x0 += ks2; x1 += k0 + 5u;
#undef TFR
    o0 = x0; o1 = x1;
}

// ---------------------------------------------------------------------------
// G = I - P P^T  (exact fp32, serial ascending-k fma accumulation)
// ---------------------------------------------------------------------------
__global__ void g_init_kernel(const float* __restrict__ P)
{
    __shared__ float Ta[16][129];
    __shared__ float Tb[16][129];
    const int bi = blockIdx.y * 16;
    const int bj = blockIdx.x * 16;
    for (int e = threadIdx.x; e < 16 * 128; e += 256) {
        int r = e >> 7, c = e & 127;
        Ta[r][c] = P[(bi + r) * 128 + c];
        Tb[r][c] = P[(bj + r) * 128 + c];
    }
    __syncthreads();
    const int ty = threadIdx.x >> 4, tx = threadIdx.x & 15;
    float acc = 0.0f;
#pragma unroll 8
    for (int m = 0; m < 128; m++)
        acc = __fmaf_rn(Ta[ty][m], Tb[tx][m], acc);
    const int gi = bi + ty, gj = bj + tx;
    g_A[gi * DN + gj] = __fsub_rn((gi == gj) ? 1.0f : 0.0f, acc);
}

// ---------------------------------------------------------------------------
// Precompute gumbel noise — JAX partitionable threefry bits path (bit-exact)
// ---------------------------------------------------------------------------
__global__ void gumbel_init_kernel()
{
    const int k = blockIdx.x;      // step
    const int i = threadIdx.x;     // position 0..255
    uint32_t kk0, kk1;
    threefry(0u, 42u, 0u, (uint32_t)k, kk0, kk1);     // fold_in(key(42), k)
    uint32_t o0, o1;
    threefry(kk0, kk1, 0u, (uint32_t)i, o0, o1);      // counter64 = i
    const uint32_t bits = o0 ^ o1;                     // 64->32 fold
    const float f = __uint_as_float((bits >> 9) | 0x3f800000u) - 1.0f;
    const float TINYF = 1.17549435e-38f;
    const float uu = fmaxf(TINYF, __fadd_rn(f, TINYF));
    const float nl = (float)(-log((double)uu));
    const float g  = -(float)(log((double)nl));
    g_gum[k * DN + i] = g;
}

__device__ __forceinline__ float piv_safe_rcp(float pv)
{
    const float pvs = (fabsf(pv) > 1e-30f) ? pv : 1e-30f;
    return __frcp_rn(pvs);
}

__device__ __forceinline__ int ld_acq_shared(const int* p)
{
    int v;
    uint32_t a = (uint32_t)__cvta_generic_to_shared((void*)p);
    asm volatile("ld.acquire.cta.shared.b32 %0, [%1];" : "=r"(v) : "r"(a) : "memory");
    return v;
}

__device__ __forceinline__ void st_rel_shared(int* p, int v)
{
    uint32_t a = (uint32_t)__cvta_generic_to_shared((void*)p);
    asm volatile("st.release.cta.shared.b32 [%0], %1;" :: "r"(a), "r"(v) : "memory");
}

// ---------------------------------------------------------------------------
// Persistent single-CTA sampler: 128 sequential steps (incremental front).
// Spec LU = warp wavefront with hot-spin ONLY on the critical-path warp;
// all other warps poll with nanosleep backoff. Copy fused into wavefront.
// ---------------------------------------------------------------------------
__global__ __launch_bounds__(NTHREADS, 1)
void sampler_kernel(float* __restrict__ out, int out_size)
{
    extern __shared__ float S[];          // scratch block, SD-stride rows
    __shared__ float piv[DN];
    __shared__ float occ[DN];
    __shared__ float rinvs[SD];
    __shared__ int   flags[SD];
    __shared__ float sh_rinv;
    __shared__ int   sh_t, sh_pos;
    __shared__ float sh_ps;

    const int tid = threadIdx.x;
    const int wid = tid >> 5, lid = tid & 31;
    const float NEGINF = __int_as_float(0xff800000);

    for (int i = tid; i < DN; i += NTHREADS) {
        occ[i] = 0.0f;
        g_dv1[i] = __fsub_rn(g_A[i * DN + i], 1.0f);
    }
    if (tid == 0) { sh_t = 0; sh_ps = 1.0f; }
    __syncthreads();

    for (int k = 0; k < NN; k++) {
        const int t = sh_t;
        const int xmax = DN - NN + k + 1;   // 129 + k
        const int s = xmax - t;             // <= 129

        // ---- reset handoff flags ----
        for (int i = tid; i < SD; i += NTHREADS) flags[i] = 0;
        __syncthreads();

        // ---- fused copy (each warp copies its owned rows) + seed pivot 0 ----
        if (wid == 0) {
            // row 0 first, publish immediately so the wavefront can start
            {
                const float* src = g_A + t * DN + t;
                for (int c = lid; c < s; c += 32) S[c] = src[c];
            }
            __syncwarp();
            if (lid == 0) {
                const float pv = S[0];
                piv[t] = pv;
                rinvs[0] = piv_safe_rcp(pv);
                st_rel_shared(&flags[0], 1);
            }
            for (int r = 32; r < s; r += 32) {
                const float* src = g_A + (t + r) * DN + t;
                float* dst = S + r * SD;
                for (int c = lid; c < s; c += 32) dst[c] = src[c];
            }
        } else {
            for (int r = wid; r < s; r += 32) {
                const float* src = g_A + (t + r) * DN + t;
                float* dst = S + r * SD;
                for (int c = lid; c < s; c += 32) dst[c] = src[c];
            }
        }

        // ---- wavefront speculative elimination (no CTA barriers) ----
        // li = A[i,j] * rcp(piv_safe);  A[i,c] = fma(-li, A[j,c], A[i,c])
        for (int j = 0; j < s - 1; j++) {
            const int base = j + 1;
            const int rstart = base + ((wid - (base & 31)) & 31);
            if (rstart >= s) break;               // no owned rows remain
            if (rstart == base) {
                // critical-path warp: hot spin
                while (ld_acq_shared(&flags[j]) == 0) {}
            } else {
                // off-path warps: polite poll with backoff
                int bo = 0;
                while (ld_acq_shared(&flags[j]) == 0) {
                    __nanosleep(32u << (bo < 3 ? bo : 3));
                    bo++;
                }
            }
            const float rinv = rinvs[j];
            const int cc = base + lid;
            const float* uro = S + j * SD;
            const float u0 = (cc      < s) ? uro[cc     ] : 0.0f;
            const float u1 = (cc + 32 < s) ? uro[cc + 32] : 0.0f;
            const float u2 = (cc + 64 < s) ? uro[cc + 64] : 0.0f;
            const float u3 = (cc + 96 < s) ? uro[cc + 96] : 0.0f;
            for (int i = rstart; i < s; i += 32) {
                const float li = __fmul_rn(S[i * SD + j], rinv);
                float* row = S + i * SD;
                float vdiag = 0.0f;
                if (cc < s) { vdiag = __fmaf_rn(-li, u0, row[cc]); row[cc] = vdiag; }
                if (cc + 32 < s) row[cc + 32] = __fmaf_rn(-li, u1, row[cc + 32]);
                if (cc + 64 < s) row[cc + 64] = __fmaf_rn(-li, u2, row[cc + 64]);
                if (cc + 96 < s) row[cc + 96] = __fmaf_rn(-li, u3, row[cc + 96]);
                if (i == base) {                  // publish pivot row j+1
                    if (lid == 0) { piv[t + i] = vdiag; rinvs[i] = piv_safe_rcp(vdiag); }
                    __syncwarp();
                    if (lid == 0) st_rel_shared(&flags[i], 1);
                }
            }
        }
        __syncthreads();

        // ---- single-warp sampling: scan + probs + gumbel argmax ----
        if (wid == 0) {
            const int ch = (s + 31) >> 5;         // <= 5 slots per lane
            const int lo = lid * ch;
            float u[5], gum[5];
            float lp = 1.0f;
#pragma unroll
            for (int m = 0; m < 5; m++) {
                const int idx = lo + m;
                const bool ok = (m < ch) && (idx < s);
                u[m]   = ok ? piv[t + idx] : 1.0f;
                gum[m] = ok ? g_gum[k * DN + (t + idx)] : 0.0f;
                lp = __fmul_rn(lp, u[m]);
            }
            float run = lp;
            for (int d = 1; d < 32; d <<= 1) {
                const float v = __shfl_up_sync(0xffffffffu, run, d);
                if (lid >= d) run = __fmul_rn(v, run);
            }
            float c = __shfl_up_sync(0xffffffffu, run, 1);
            if (lid == 0) c = 1.0f;

            float best = NEGINF, bprob = 0.0f;
            int bidx = 1 << 30;
#pragma unroll
            for (int m = 0; m < 5; m++) {
                const int idx = lo + m;
                if (m < ch && idx < s) {
                    float p = __fmul_rn(__fsub_rn(1.0f, u[m]), c);
                    p = (fabsf(p) > 1e-15f) ? p : 0.0f;
                    c = __fmul_rn(c, u[m]);
                    if (p > 0.0f) {
                        const float vv = __fadd_rn(gum[m], logf(p));
                        if (vv > best) { best = vv; bidx = idx; bprob = p; }
                    }
                }
            }
            for (int off = 16; off; off >>= 1) {
                const float ov = __shfl_down_sync(0xffffffffu, best, off);
                const int   oi = __shfl_down_sync(0xffffffffu, bidx, off);
                const float op = __shfl_down_sync(0xffffffffu, bprob, off);
                if (ov > best || (ov == best && oi < bidx)) { best = ov; bidx = oi; bprob = op; }
            }
            if (lid == 0) {
                const int pos = (bidx == (1 << 30)) ? 0 : (t + bidx);
                const float psel = (bidx == (1 << 30)) ? 0.0f : bprob;
                sh_pos = pos;
                occ[pos] = 1.0f;
                sh_ps = __fmul_rn(sh_ps, psel);
            }
        }
        __syncthreads();

        // ---- commit rows t..pos into master (advance front to pos+1) ----
        const int pos = sh_pos;
        if (k < NN - 1) {
            for (int j = t; j <= pos; j++) {
                if (tid == 0) {
                    if (j == pos)
                        g_A[pos * DN + pos] = g_dv1[pos];   // -1-from-step-0 chain
                    sh_rinv = piv_safe_rcp(g_A[j * DN + j]);
                }
                __syncthreads();
                const float rinv = sh_rinv;
                const int cc = j + 1 + lid;
                const float* uro = g_A + j * DN;
                float uu[8];
#pragma unroll
                for (int m = 0; m < 8; m++) {
                    const int c = cc + 32 * m;
                    uu[m] = (c < DN) ? uro[c] : 0.0f;
                }
                for (int i = j + 1 + wid; i < DN; i += NWARPS) {
                    const float li = __fmul_rn(g_A[i * DN + j], rinv);
                    float* row = g_A + i * DN;
#pragma unroll
                    for (int m = 0; m < 8; m++) {
                        const int c = cc + 32 * m;
                        if (c < DN) {
                            row[c] = __fmaf_rn(-li, uu[m], row[c]);
                            if (c == i) g_dv1[i] = __fmaf_rn(-li, uu[m], g_dv1[i]);
                        }
                    }
                }
                __syncthreads();
            }
            if (tid == 0) sh_t = pos + 1;
        }
        __syncthreads();
    }

    // ---- outputs: occ_vec (256) then prob_sample (1) ----
    for (int i = tid; i < DN && i < out_size; i += NTHREADS) out[i] = occ[i];
    if (tid == 0 && out_size > DN) out[DN] = sh_ps;
    for (int i = DN + 1 + tid; i < out_size; i += NTHREADS) out[i] = 0.0f;
}

// ---------------------------------------------------------------------------
extern "C" void kernel_launch(void* const* d_in, const int* in_sizes, int n_in,
                              void* d_out, int out_size)
{
    const float* P = (const float*)d_in[0];
    float* out = (float*)d_out;

    cudaFuncSetAttribute(sampler_kernel,
                         cudaFuncAttributeMaxDynamicSharedMemorySize,
                         SMEM_BYTES);

    g_init_kernel<<<dim3(16, 16), 256>>>(P);
    gumbel_init_kernel<<<NN, DN>>>();
    sampler_kernel<<<1, NTHREADS, SMEM_BYTES>>>(out, out_size);
}